// round 17
// baseline (speedup 1.0000x reference)
#include <cuda_runtime.h>

// ---------------- problem constants ----------------
#define NB      4096
#define NNOTES  48
#define NF      256
#define NU      256
#define NG      1024      // 4 * NU (i,f,g,o), interleaved [unit][gate]
#define K0TOT   520       // ih0 (259) + pad(1) + hh0 (256) + pad(4)
#define K1TOT   520       // ih1 (256) + hh1 (256) + pad(8)
#define MROWS   32        // batch rows per CTA
#define NTHR    1024
#define ASTR    36        // transposed-A row stride (32 rows + 4 pad)

typedef unsigned long long u64;

// ---------------- device scratch (static, allocation-guard-safe) ----------------
__device__ __align__(16) float g_W0[K0TOT * NG];   // [k][unit*4+gate], pad rows zero
__device__ __align__(16) float g_W1[K1TOT * NG];   // [k][unit*4+gate], pad rows zero
__device__ __align__(16) float g_b0[NG];           // [unit*4+gate]
__device__ __align__(16) float g_b1[NG];
__device__ __align__(16) float g_c0[NB * NU];      // layer-0 cell state (L2-resident)
__device__ __align__(16) float g_c1[NB * NU];      // layer-1 cell state

// ---------------- helpers ----------------
__device__ __forceinline__ u64 pack2(float x) {
    u64 r;
    asm("mov.b64 %0, {%1, %1};" : "=l"(r) : "r"(__float_as_uint(x)));
    return r;
}
__device__ __forceinline__ void fma2(u64& acc, u64 a, u64 b) {
    asm("fma.rn.f32x2 %0, %1, %2, %0;" : "+l"(acc) : "l"(a), "l"(b));
}
__device__ __forceinline__ void unpack2(u64 v, float& lo, float& hi) {
    unsigned int a, b;
    asm("mov.b64 {%0, %1}, %2;" : "=r"(a), "=r"(b) : "l"(v));
    lo = __uint_as_float(a);
    hi = __uint_as_float(b);
}
__device__ __forceinline__ float sigf(float x) {
    return 1.0f / (1.0f + expf(-x));
}

// ---------------- prep: transpose + interleave + concatenate weights ----------------
__global__ void prep_kernel(const float* __restrict__ W_ih0, const float* __restrict__ W_hh0,
                            const float* __restrict__ b_ih0, const float* __restrict__ b_hh0,
                            const float* __restrict__ W_ih1, const float* __restrict__ W_hh1,
                            const float* __restrict__ b_ih1, const float* __restrict__ b_hh1) {
    int tid = blockIdx.x * blockDim.x + threadIdx.x;
    int stride = gridDim.x * blockDim.x;
    for (int i = tid; i < K0TOT * NG; i += stride) {
        int k = i >> 10, j = i & 1023;
        int u = j >> 2, g = j & 3;
        int orow = g * 256 + u;              // original row in [4*NU, K] weight
        float v = 0.f;
        if (k < 259)                  v = W_ih0[orow * 259 + k];
        else if (k >= 260 && k < 516) v = W_hh0[orow * 256 + (k - 260)];
        g_W0[i] = v;                          // rows 259, 516..519 stay zero
    }
    for (int i = tid; i < K1TOT * NG; i += stride) {
        int k = i >> 10, j = i & 1023;
        int u = j >> 2, g = j & 3;
        int orow = g * 256 + u;
        float v = 0.f;
        if (k < 256)       v = W_ih1[orow * 256 + k];
        else if (k < 512)  v = W_hh1[orow * 256 + (k - 256)];
        g_W1[i] = v;                          // rows 512..519 stay zero
    }
    for (int i = tid; i < NG; i += stride) {
        int u = i >> 2, g = i & 3;
        int orow = g * 256 + u;
        g_b0[i] = b_ih0[orow] + b_hh0[orow];
        g_b1[i] = b_ih1[orow] + b_hh1[orow];
    }
}

// ---------------- one k-slice of FMAs ----------------
__device__ __forceinline__ void fma_k(u64 (&acc)[4][4], const float* ab, float4 w4) {
    ulonglong2 av0 = *(const ulonglong2*)(ab);      // rows 0-3 (bcast LDS.128)
    ulonglong2 av1 = *(const ulonglong2*)(ab + 4);  // rows 4-7 (bcast LDS.128)
    u64 wi = pack2(w4.x);
    u64 wf = pack2(w4.y);
    u64 wg = pack2(w4.z);
    u64 wo = pack2(w4.w);
    fma2(acc[0][0], av0.x, wi); fma2(acc[1][0], av0.y, wi);
    fma2(acc[2][0], av1.x, wi); fma2(acc[3][0], av1.y, wi);
    fma2(acc[0][1], av0.x, wf); fma2(acc[1][1], av0.y, wf);
    fma2(acc[2][1], av1.x, wf); fma2(acc[3][1], av1.y, wf);
    fma2(acc[0][2], av0.x, wg); fma2(acc[1][2], av0.y, wg);
    fma2(acc[2][2], av1.x, wg); fma2(acc[3][2], av1.y, wg);
    fma2(acc[0][3], av0.x, wo); fma2(acc[1][3], av0.y, wo);
    fma2(acc[2][3], av1.x, wo); fma2(acc[3][3], av1.y, wo);
}

// ---------------- GEMM over one layer: W global->register, SW-pipelined ----------------
// Thread (rg = tid>>8, ug = tid&255): rows rg*8..rg*8+7 (f32x2 lanes = row pairs),
// unit ug, all 4 gates. A transposed in smem (broadcast LDS); W loaded straight
// from global, REGISTER DOUBLE-BUFFERED at batch=2: rows k0+2,k0+3 are in flight
// while k0,k0+1 compute -> LDG latency hidden by a full batch of FMAs x 8 warps.
// No barriers inside the loop: warps drift and self-hide residual latency.
__device__ __forceinline__ void gemm_layer(
    u64 (&acc)[4][4],
    const float* A,                      // contiguous [520][ASTR] in smem
    const float* __restrict__ Wg,        // [ktot][NG] in global
    int ktot, int rg8, int ug)
{
    const float4* __restrict__ wp = (const float4*)Wg + ug;   // stride NG/4 per k
    float4 wa0 = __ldg(wp);
    float4 wa1 = __ldg(wp + (NG / 4));
    const float* ab = A + rg8;
    for (int k0 = 0; k0 < ktot; k0 += 2) {
        // prefetch next batch (clamped near the tail: value discarded, stays in-bounds)
        int kn = (k0 + 2 < ktot) ? (k0 + 2) : 0;
        float4 wb0 = __ldg(wp + (size_t)kn * (NG / 4));
        float4 wb1 = __ldg(wp + (size_t)(kn + 1) * (NG / 4));
        // compute current batch
        fma_k(acc, ab, wa0);
        fma_k(acc, ab + ASTR, wa1);
        wa0 = wb0;
        wa1 = wb1;
        ab += 2 * ASTR;
    }
}

// ---------------- LSTM cell elementwise ----------------
// Thread owns rows rg8..rg8+7 (4 lane-pairs) and unit ug.
// c in prefetched registers -> coalesced STG to L2-resident scratch.
__device__ __forceinline__ void cell_update(
    u64 (&acc)[4][4], const float (&cin)[8], float* __restrict__ cg,
    float* hT, int rg8, int ug)
{
    float hn[8];
#pragma unroll
    for (int rp = 0; rp < 4; rp++) {
        float i0, i1, f0, f1, g0, g1, o0, o1;
        unpack2(acc[rp][0], i0, i1);
        unpack2(acc[rp][1], f0, f1);
        unpack2(acc[rp][2], g0, g1);
        unpack2(acc[rp][3], o0, o1);
        float cn0 = sigf(f0) * cin[2 * rp]     + sigf(i0) * tanhf(g0);
        float cn1 = sigf(f1) * cin[2 * rp + 1] + sigf(i1) * tanhf(g1);
        int r0 = rg8 + 2 * rp;
        cg[r0 * NU + ug]       = cn0;   // coalesced STG.32
        cg[(r0 + 1) * NU + ug] = cn1;
        hn[2 * rp]     = sigf(o0) * tanhf(cn0);
        hn[2 * rp + 1] = sigf(o1) * tanhf(cn1);
    }
    __syncthreads();   // all GEMM readers of old hT are done
    float4* d = (float4*)(hT + ug * ASTR + rg8);
    d[0] = make_float4(hn[0], hn[1], hn[2], hn[3]);
    d[1] = make_float4(hn[4], hn[5], hn[6], hn[7]);
    __syncthreads();   // new hT visible (output head / next GEMM)
}

// ---------------- main persistent kernel ----------------
__global__ void __launch_bounds__(NTHR, 1)
noteaxis_kernel(const float* __restrict__ feats,
                const float* __restrict__ cond,
                const float* __restrict__ Wout,
                const float* __restrict__ bout,
                float* __restrict__ out)
{
    extern __shared__ float smem[];
    float* sh_xT  = smem;                 // 260 rows
    float* sh_h0T = sh_xT + 260 * ASTR;   // 256 rows (contiguous after xT)
    float* sh_h1T = sh_h0T + NU * ASTR;   // 256 rows + 8 zero pad rows

    int tid = threadIdx.x;
    int rg  = tid >> 8;        // 0..3, warp-uniform
    int ug  = tid & 255;       // unit index
    int rg8 = rg * 8;
    size_t batch0 = (size_t)blockIdx.x * MROWS;

    float* c0g = g_c0 + batch0 * NU;
    float* c1g = g_c1 + batch0 * NU;

    // zero h0T, h1T and the 8 pad rows after h1T (pad x zero-W must stay finite)
    for (int i = tid; i < (2 * NU + 8) * ASTR; i += NTHR) sh_h0T[i] = 0.f;
    __syncthreads();

    for (int n = 0; n < NNOTES; n++) {
        // ---- stage x TRANSPOSED: xT[c][r]; coalesced global reads, scattered STS ----
        for (int idx = tid; idx < MROWS * NF; idx += NTHR) {
            int r = idx >> 8;          // NF = 256
            int c = idx & 255;
            sh_xT[c * ASTR + r] = feats[((batch0 + r) * NNOTES + n) * NF + c];
        }
        if (tid < MROWS * 4) {
            int r = tid >> 2, j = tid & 3;
            float v = 0.f;
            if (j < 3 && n > 0) v = cond[((batch0 + r) * NNOTES + (n - 1)) * 3 + j];
            sh_xT[(NF + j) * ASTR + r] = v;   // cols 256..258 = shifted cond, 259 = pad
        }
        __syncthreads();   // x tile visible before layer-0 GEMM reads it

        u64 acc[4][4];
        float cpre[8];

        // ---- layer 0: gates = [x ++ h0_prev (++ h1 data x zero-W)] @ W0 + b0 ----
#pragma unroll
        for (int rp = 0; rp < 8; rp++)
            cpre[rp] = (n == 0) ? 0.f : c0g[(rg8 + rp) * NU + ug];   // hidden by GEMM
        {
            float4 b4 = *(const float4*)(g_b0 + ug * 4);
            u64 bi = pack2(b4.x), bf = pack2(b4.y), bg = pack2(b4.z), bo = pack2(b4.w);
#pragma unroll
            for (int rp = 0; rp < 4; rp++) {
                acc[rp][0] = bi; acc[rp][1] = bf; acc[rp][2] = bg; acc[rp][3] = bo;
            }
        }
        gemm_layer(acc, sh_xT, g_W0, K0TOT, rg8, ug);
        cell_update(acc, cpre, c0g, sh_h0T, rg8, ug);

        // ---- layer 1: gates = [h0_new ++ h1_prev (++ zero pad)] @ W1 + b1 ----
#pragma unroll
        for (int rp = 0; rp < 8; rp++)
            cpre[rp] = (n == 0) ? 0.f : c1g[(rg8 + rp) * NU + ug];
        {
            float4 b4 = *(const float4*)(g_b1 + ug * 4);
            u64 bi = pack2(b4.x), bf = pack2(b4.y), bg = pack2(b4.z), bo = pack2(b4.w);
#pragma unroll
            for (int rp = 0; rp < 4; rp++) {
                acc[rp][0] = bi; acc[rp][1] = bf; acc[rp][2] = bg; acc[rp][3] = bo;
            }
        }
        gemm_layer(acc, sh_h0T, g_W1, K1TOT, rg8, ug);
        cell_update(acc, cpre, c1g, sh_h1T, rg8, ug);

        // ---- output head: out[b,n,ch] = sigmoid?(h1 . Wout[ch] + bout[ch]) ----
        if (tid < MROWS * 3) {
            int r = tid / 3, ch = tid - r * 3;
            const float* wv = Wout + ch * NU;
            float s = bout[ch];
#pragma unroll 8
            for (int u2 = 0; u2 < NU; u2++)
                s += sh_h1T[u2 * ASTR + r] * wv[u2];
            if (ch < 2) s = sigf(s);
            out[((batch0 + r) * NNOTES + n) * 3 + ch] = s;
        }
        __syncthreads();   // h1T readers (output head) done before next overwrite
    }
}

// ---------------- launch ----------------
extern "C" void kernel_launch(void* const* d_in, const int* in_sizes, int n_in,
                              void* d_out, int out_size)
{
    const float* feats = (const float*)d_in[0];
    const float* cond  = (const float*)d_in[1];
    const float* W_ih0 = (const float*)d_in[2];
    const float* W_hh0 = (const float*)d_in[3];
    const float* b_ih0 = (const float*)d_in[4];
    const float* b_hh0 = (const float*)d_in[5];
    const float* W_ih1 = (const float*)d_in[6];
    const float* W_hh1 = (const float*)d_in[7];
    const float* b_ih1 = (const float*)d_in[8];
    const float* b_hh1 = (const float*)d_in[9];
    const float* W_out = (const float*)d_in[10];
    const float* b_out = (const float*)d_in[11];
    float* out = (float*)d_out;

    prep_kernel<<<264, 256>>>(W_ih0, W_hh0, b_ih0, b_hh0, W_ih1, W_hh1, b_ih1, b_hh1);

    int smem_bytes = (260 * ASTR + (2 * NU + 8) * ASTR) * (int)sizeof(float);
    // = 780 * 36 * 4 = 112,320 B
    cudaFuncSetAttribute(noteaxis_kernel,
                         cudaFuncAttributeMaxDynamicSharedMemorySize, smem_bytes);
    noteaxis_kernel<<<NB / MROWS, NTHR, smem_bytes>>>(feats, cond, W_out, b_out, out);
}